// round 3
// baseline (speedup 1.0000x reference)
#include <cuda_runtime.h>
#include <cuda_bf16.h>
#include <cstdint>
#include <cstddef>

// Problem constants
#define BB   256
#define TT   1024
#define FF   64
#define HH   128
#define GG   512   // 4*H

// ---------------------------------------------------------------------------
// Scratch (device globals; allocation in kernel_launch is forbidden)
// ---------------------------------------------------------------------------
// xg[b][t][512] : input-gate preactivations incl. both biases  (512 MB)
__device__ float g_xg[(size_t)BB * TT * GG];
// hs[b][t][128] : hidden states for the output projection       (128 MB)
__device__ float g_hs[(size_t)BB * TT * HH];

// ---------------------------------------------------------------------------
// K1:  xg = x @ W_ih^T + (b_ih + b_hh)
//   x: [BT, 64], W_ih: [512, 64]. Tile: 32 bt-rows x 128 gates per block.
// ---------------------------------------------------------------------------
__global__ __launch_bounds__(256) void k1_xgemm(
    const float* __restrict__ x,
    const float* __restrict__ Wih,
    const float* __restrict__ bih,
    const float* __restrict__ bhh)
{
    __shared__ __align__(16) float xs[32][64];    // 8 KB
    __shared__ __align__(16) float ws[64][128];   // 32 KB, [k][gate] transposed

    const int bt0 = blockIdx.x * 32;
    const int g0  = blockIdx.y * 128;
    const int t   = threadIdx.x;

    // load x tile (2048 floats = 512 float4), coalesced
    for (int i = t; i < 512; i += 256) {
        int row = i >> 4;
        int kq  = i & 15;
        ((float4*)xs[row])[kq] =
            ((const float4*)(x + (size_t)(bt0 + row) * FF))[kq];
    }
    // load W tile transposed (128 gates x 64 k = 2048 float4 reads)
    for (int i = t; i < 2048; i += 256) {
        int g  = i >> 4;
        int kq = i & 15;
        float4 v = ((const float4*)(Wih + (size_t)(g0 + g) * FF))[kq];
        int k = kq * 4;
        ws[k + 0][g] = v.x;
        ws[k + 1][g] = v.y;
        ws[k + 2][g] = v.z;
        ws[k + 3][g] = v.w;
    }
    __syncthreads();

    const int tg = t & 31;   // gate-quad index (32 quads = 128 gates)
    const int tr = t >> 5;   // 0..7 -> rows tr*4 + i
    const int gg = g0 + tg * 4;

    float4 bias = *(const float4*)(bih + gg);
    float4 b2   = *(const float4*)(bhh + gg);
    bias.x += b2.x; bias.y += b2.y; bias.z += b2.z; bias.w += b2.w;

    float4 acc[4];
#pragma unroll
    for (int i = 0; i < 4; i++) acc[i] = bias;

#pragma unroll
    for (int k = 0; k < 64; k++) {
        float4 w4 = *(float4*)&ws[k][tg * 4];
#pragma unroll
        for (int i = 0; i < 4; i++) {
            float xv = xs[tr * 4 + i][k];
            acc[i].x += xv * w4.x;
            acc[i].y += xv * w4.y;
            acc[i].z += xv * w4.z;
            acc[i].w += xv * w4.w;
        }
    }
#pragma unroll
    for (int i = 0; i < 4; i++) {
        int row = tr * 4 + i;
        *(float4*)(g_xg + (size_t)(bt0 + row) * GG + gg) = acc[i];
    }
}

// ---------------------------------------------------------------------------
// K2: persistent LSTM recurrence.
//   64 clusters x 2 CTAs. Cluster c owns batch rows 4c..4c+3.
//   CTA rank r holds W_hh[:, 64r : 64r+64] in registers (thread t = gate t,
//   64 floats each) and owns h-columns [64r, 64r+64).
//   Per step: split-K partials for all 512 gates x 4 rows -> exchange the
//   peer-owned half via DSMEM -> cluster barrier -> pointwise update.
//   The h-half a CTA produces is exactly its K-input next step: no h exchange.
// ---------------------------------------------------------------------------
__device__ __forceinline__ float sigm(float v) {
    return 1.0f / (1.0f + expf(-v));
}

__global__ __launch_bounds__(512, 1) __cluster_dims__(2, 1, 1)
void k2_lstm(const float* __restrict__ Whh)
{
    __shared__ __align__(16) float hbuf[64][4];            // my h-half, [kLocal][row]
    __shared__ __align__(16) float pbuf[2][2][4][64][4];   // [parity][src][gt][j][row] 16 KB

    const int t    = threadIdx.x;          // == global gate index
    const int rank = blockIdx.x & 1;
    const int cid  = blockIdx.x >> 1;
    const int rowBase = cid * 4;
    const int kOff = rank * 64;

    // --- load my W_hh row-half into registers ---
    float w[64];
    {
        const float4* wp = (const float4*)(Whh + (size_t)t * HH + kOff);
#pragma unroll
        for (int q = 0; q < 16; q++) {
            float4 v = wp[q];
            w[4 * q + 0] = v.x;
            w[4 * q + 1] = v.y;
            w[4 * q + 2] = v.z;
            w[4 * q + 3] = v.w;
        }
    }

    // gate decomposition for partial routing
    const int gt    = t >> 7;        // gate type 0..3 (i,f,g,o)
    const int jg    = t & 127;       // h column of this gate
    const int owner = jg >> 6;       // which CTA owns that h column
    const int jl    = jg & 63;       // column local to owner
    const bool remote = (owner != rank);

    // destination for my 4-row partial vector (precompute address once)
    float* localDst = &pbuf[0][rank][gt][jl][0];
    uint32_t remoteAddr = 0;
    if (remote) {
        uint32_t la = (uint32_t)__cvta_generic_to_shared(localDst);
        asm volatile("mapa.shared::cluster.u32 %0, %1, %2;"
                     : "=r"(remoteAddr) : "r"(la), "r"(owner));
    }
    const uint32_t PAR_STRIDE = 2u * 4u * 64u * 4u * 4u;   // 8192 bytes

    // pointwise identity (first 256 threads): thread = (j, row)
    const int pj = t >> 2;
    const int pr = t & 3;
    const int pb = rowBase + pr;   // global batch row

    // init
    if (t < 256) hbuf[pj][pr] = 0.0f;
    float c = 0.0f;
    __syncthreads();

    const float4* h4 = (const float4*)hbuf;

    for (int step = 0; step < TT; step++) {
        const int par = step & 1;

        // prefetch this step's xg for my 4 owned gates (long-latency,
        // consumed only after the cluster barrier -> hidden under phase A)
        float xg0 = 0.f, xg1 = 0.f, xg2 = 0.f, xg3 = 0.f;
        if (t < 256) {
            size_t base = ((size_t)pb * TT + step) * GG + (size_t)(rank * 64 + pj);
            xg0 = g_xg[base];
            xg1 = g_xg[base + 128];
            xg2 = g_xg[base + 256];
            xg3 = g_xg[base + 384];
        }

        // --- phase A: split-K partial dot products (4 rows per thread) ---
        float ax = 0.f, ay = 0.f, az = 0.f, aw = 0.f;
#pragma unroll
        for (int k = 0; k < 64; k++) {
            float4 hv = h4[k];           // broadcast LDS.128
            ax += w[k] * hv.x;
            ay += w[k] * hv.y;
            az += w[k] * hv.z;
            aw += w[k] * hv.w;
        }

        // --- route partials to the owning CTA ---
        if (!remote) {
            float4 v = make_float4(ax, ay, az, aw);
            *(float4*)((char*)localDst + par * PAR_STRIDE) = v;
        } else {
            uint32_t a = remoteAddr + par * PAR_STRIDE;
            asm volatile("st.shared::cluster.f32 [%0], %1;" :: "r"(a),      "f"(ax) : "memory");
            asm volatile("st.shared::cluster.f32 [%0], %1;" :: "r"(a + 4),  "f"(ay) : "memory");
            asm volatile("st.shared::cluster.f32 [%0], %1;" :: "r"(a + 8),  "f"(az) : "memory");
            asm volatile("st.shared::cluster.f32 [%0], %1;" :: "r"(a + 12), "f"(aw) : "memory");
        }

        // cluster rendezvous: release my stores, acquire peer's
        asm volatile("barrier.cluster.arrive.aligned;" ::: "memory");
        asm volatile("barrier.cluster.wait.aligned;"   ::: "memory");

        // --- pointwise LSTM update for my owned (row, column) ---
        if (t < 256) {
            float gi = xg0 + pbuf[par][0][0][pj][pr] + pbuf[par][1][0][pj][pr];
            float gf = xg1 + pbuf[par][0][1][pj][pr] + pbuf[par][1][1][pj][pr];
            float gc = xg2 + pbuf[par][0][2][pj][pr] + pbuf[par][1][2][pj][pr];
            float go = xg3 + pbuf[par][0][3][pj][pr] + pbuf[par][1][3][pj][pr];

            float iv = sigm(gi);
            float fv = sigm(gf);
            float gv = tanhf(gc);
            float ov = sigm(go);

            c = fv * c + iv * gv;
            float h = ov * tanhf(c);

            hbuf[pj][pr] = h;
            g_hs[((size_t)pb * TT + step) * HH + (size_t)(rank * 64 + pj)] = h;
        }
        __syncthreads();   // h visible to all 512 threads before next phase A
    }
}

// ---------------------------------------------------------------------------
// K3: out = hs @ W_out^T.  hs: [BT, 128], W_out: [64, 128].
//   Tile: 32 bt-rows x 64 f per block. smem = 16 KB + 32 KB = 48 KB (static max).
// ---------------------------------------------------------------------------
__global__ __launch_bounds__(256) void k3_proj(
    const float* __restrict__ Wout,
    float* __restrict__ out)
{
    __shared__ __align__(16) float hs_s[32][128];   // 16 KB
    __shared__ __align__(16) float ws[128][64];     // 32 KB, [k][f] transposed

    const int bt0 = blockIdx.x * 32;
    const int t   = threadIdx.x;

    // load hs tile: 4096 floats = 1024 float4
    for (int i = t; i < 1024; i += 256) {
        int row = i >> 5;
        int q   = i & 31;
        ((float4*)hs_s[row])[q] =
            ((const float4*)(g_hs + (size_t)(bt0 + row) * HH))[q];
    }
    // load W_out transposed: 64 f x 128 k = 2048 float4
    for (int i = t; i < 2048; i += 256) {
        int f  = i >> 5;
        int kq = i & 31;
        float4 v = ((const float4*)(Wout + (size_t)f * HH))[kq];
        int k = kq * 4;
        ws[k + 0][f] = v.x;
        ws[k + 1][f] = v.y;
        ws[k + 2][f] = v.z;
        ws[k + 3][f] = v.w;
    }
    __syncthreads();

    const int tf = t & 15;    // f-quad (16 quads = 64 f)
    const int tr = t >> 4;    // 0..15 -> rows tr and tr+16

    float4 acc0 = make_float4(0.f, 0.f, 0.f, 0.f);
    float4 acc1 = make_float4(0.f, 0.f, 0.f, 0.f);

#pragma unroll
    for (int k = 0; k < 128; k++) {
        float4 w4 = *(float4*)&ws[k][tf * 4];
        float h0 = hs_s[tr][k];
        float h1 = hs_s[tr + 16][k];
        acc0.x += h0 * w4.x; acc0.y += h0 * w4.y;
        acc0.z += h0 * w4.z; acc0.w += h0 * w4.w;
        acc1.x += h1 * w4.x; acc1.y += h1 * w4.y;
        acc1.z += h1 * w4.z; acc1.w += h1 * w4.w;
    }

    *(float4*)(out + (size_t)(bt0 + tr) * FF + tf * 4)      = acc0;
    *(float4*)(out + (size_t)(bt0 + tr + 16) * FF + tf * 4) = acc1;
}

// ---------------------------------------------------------------------------
// launch
// ---------------------------------------------------------------------------
extern "C" void kernel_launch(void* const* d_in, const int* in_sizes, int n_in,
                              void* d_out, int out_size)
{
    const float* x    = (const float*)d_in[0];  // [256,1024,64]
    const float* Wih  = (const float*)d_in[1];  // [512,64]
    const float* Whh  = (const float*)d_in[2];  // [512,128]
    const float* bih  = (const float*)d_in[3];  // [512]
    const float* bhh  = (const float*)d_in[4];  // [512]
    const float* Wout = (const float*)d_in[5];  // [64,128]
    float* out = (float*)d_out;                 // [256,1024,64]

    (void)in_sizes; (void)n_in; (void)out_size;

    // K1: xg precompute. Grid: (BT/32) x 4 gate-tiles of 128.
    k1_xgemm<<<dim3((BB * TT) / 32, 4), 256>>>(x, Wih, bih, bhh);

    // K2: persistent recurrence. 64 clusters x 2 CTAs (cluster dims compiled in).
    k2_lstm<<<128, 512>>>(Whh);

    // K3: output projection.
    k3_proj<<<(BB * TT) / 32, 256>>>(Wout, out);
}

// round 4
// speedup vs baseline: 1.0009x; 1.0009x over previous
#include <cuda_runtime.h>
#include <cuda_bf16.h>
#include <cstdint>
#include <cstddef>

// Problem constants
#define BB   256
#define TT   1024
#define FF   64
#define HH   128
#define GG   512   // 4*H

// ---------------------------------------------------------------------------
// Scratch (device globals; allocation in kernel_launch is forbidden)
// ---------------------------------------------------------------------------
// xg[b][t][512] : input-gate preactivations incl. both biases  (512 MB)
__device__ float g_xg[(size_t)BB * TT * GG];
// hs[b][t][128] : hidden states for the output projection       (128 MB)
__device__ float g_hs[(size_t)BB * TT * HH];

// ---------------------------------------------------------------------------
// K1:  xg = x @ W_ih^T + (b_ih + b_hh)
//   x: [BT, 64], W_ih: [512, 64]. Tile: 32 bt-rows x 128 gates per block.
// ---------------------------------------------------------------------------
__global__ __launch_bounds__(256) void k1_xgemm(
    const float* __restrict__ x,
    const float* __restrict__ Wih,
    const float* __restrict__ bih,
    const float* __restrict__ bhh)
{
    __shared__ __align__(16) float xs[32][64];    // 8 KB
    __shared__ __align__(16) float ws[64][128];   // 32 KB, [k][gate] transposed

    const int bt0 = blockIdx.x * 32;
    const int g0  = blockIdx.y * 128;
    const int t   = threadIdx.x;

    // load x tile (2048 floats = 512 float4), coalesced
    for (int i = t; i < 512; i += 256) {
        int row = i >> 4;
        int kq  = i & 15;
        ((float4*)xs[row])[kq] =
            ((const float4*)(x + (size_t)(bt0 + row) * FF))[kq];
    }
    // load W tile transposed (128 gates x 64 k = 2048 float4 reads)
    for (int i = t; i < 2048; i += 256) {
        int g  = i >> 4;
        int kq = i & 15;
        float4 v = ((const float4*)(Wih + (size_t)(g0 + g) * FF))[kq];
        int k = kq * 4;
        ws[k + 0][g] = v.x;
        ws[k + 1][g] = v.y;
        ws[k + 2][g] = v.z;
        ws[k + 3][g] = v.w;
    }
    __syncthreads();

    const int tg = t & 31;   // gate-quad index (32 quads = 128 gates)
    const int tr = t >> 5;   // 0..7 -> rows tr*4 + i
    const int gg = g0 + tg * 4;

    float4 bias = *(const float4*)(bih + gg);
    float4 b2   = *(const float4*)(bhh + gg);
    bias.x += b2.x; bias.y += b2.y; bias.z += b2.z; bias.w += b2.w;

    float4 acc[4];
#pragma unroll
    for (int i = 0; i < 4; i++) acc[i] = bias;

#pragma unroll
    for (int k = 0; k < 64; k++) {
        float4 w4 = *(float4*)&ws[k][tg * 4];
#pragma unroll
        for (int i = 0; i < 4; i++) {
            float xv = xs[tr * 4 + i][k];
            acc[i].x += xv * w4.x;
            acc[i].y += xv * w4.y;
            acc[i].z += xv * w4.z;
            acc[i].w += xv * w4.w;
        }
    }
#pragma unroll
    for (int i = 0; i < 4; i++) {
        int row = tr * 4 + i;
        *(float4*)(g_xg + (size_t)(bt0 + row) * GG + gg) = acc[i];
    }
}

// ---------------------------------------------------------------------------
// K2: persistent LSTM recurrence.
//   64 clusters x 2 CTAs. Cluster c owns batch rows 4c..4c+3.
//   CTA rank r holds W_hh[:, 64r : 64r+64] in registers (thread t = gate t,
//   64 floats each) and owns h-columns [64r, 64r+64).
//   Per step: split-K partials for all 512 gates x 4 rows -> exchange the
//   peer-owned half via DSMEM -> cluster barrier -> pointwise update.
//   The h-half a CTA produces is exactly its K-input next step: no h exchange.
// ---------------------------------------------------------------------------
__device__ __forceinline__ float sigm(float v) {
    return 1.0f / (1.0f + expf(-v));
}

__global__ __launch_bounds__(512, 1) __cluster_dims__(2, 1, 1)
void k2_lstm(const float* __restrict__ Whh)
{
    __shared__ __align__(16) float hbuf[64][4];            // my h-half, [kLocal][row]
    __shared__ __align__(16) float pbuf[2][2][4][64][4];   // [parity][src][gt][j][row] 16 KB

    const int t    = threadIdx.x;          // == global gate index
    const int rank = blockIdx.x & 1;
    const int cid  = blockIdx.x >> 1;
    const int rowBase = cid * 4;
    const int kOff = rank * 64;

    // --- load my W_hh row-half into registers ---
    float w[64];
    {
        const float4* wp = (const float4*)(Whh + (size_t)t * HH + kOff);
#pragma unroll
        for (int q = 0; q < 16; q++) {
            float4 v = wp[q];
            w[4 * q + 0] = v.x;
            w[4 * q + 1] = v.y;
            w[4 * q + 2] = v.z;
            w[4 * q + 3] = v.w;
        }
    }

    // gate decomposition for partial routing
    const int gt    = t >> 7;        // gate type 0..3 (i,f,g,o)
    const int jg    = t & 127;       // h column of this gate
    const int owner = jg >> 6;       // which CTA owns that h column
    const int jl    = jg & 63;       // column local to owner
    const bool remote = (owner != rank);

    // destination for my 4-row partial vector (precompute address once)
    float* localDst = &pbuf[0][rank][gt][jl][0];
    uint32_t remoteAddr = 0;
    if (remote) {
        uint32_t la = (uint32_t)__cvta_generic_to_shared(localDst);
        asm volatile("mapa.shared::cluster.u32 %0, %1, %2;"
                     : "=r"(remoteAddr) : "r"(la), "r"(owner));
    }
    const uint32_t PAR_STRIDE = 2u * 4u * 64u * 4u * 4u;   // 8192 bytes

    // pointwise identity (first 256 threads): thread = (j, row)
    const int pj = t >> 2;
    const int pr = t & 3;
    const int pb = rowBase + pr;   // global batch row

    // init
    if (t < 256) hbuf[pj][pr] = 0.0f;
    float c = 0.0f;
    __syncthreads();

    const float4* h4 = (const float4*)hbuf;

    for (int step = 0; step < TT; step++) {
        const int par = step & 1;

        // prefetch this step's xg for my 4 owned gates (long-latency,
        // consumed only after the cluster barrier -> hidden under phase A)
        float xg0 = 0.f, xg1 = 0.f, xg2 = 0.f, xg3 = 0.f;
        if (t < 256) {
            size_t base = ((size_t)pb * TT + step) * GG + (size_t)(rank * 64 + pj);
            xg0 = g_xg[base];
            xg1 = g_xg[base + 128];
            xg2 = g_xg[base + 256];
            xg3 = g_xg[base + 384];
        }

        // --- phase A: split-K partial dot products (4 rows per thread) ---
        float ax = 0.f, ay = 0.f, az = 0.f, aw = 0.f;
#pragma unroll
        for (int k = 0; k < 64; k++) {
            float4 hv = h4[k];           // broadcast LDS.128
            ax += w[k] * hv.x;
            ay += w[k] * hv.y;
            az += w[k] * hv.z;
            aw += w[k] * hv.w;
        }

        // --- route partials to the owning CTA ---
        if (!remote) {
            float4 v = make_float4(ax, ay, az, aw);
            *(float4*)((char*)localDst + par * PAR_STRIDE) = v;
        } else {
            uint32_t a = remoteAddr + par * PAR_STRIDE;
            asm volatile("st.shared::cluster.f32 [%0], %1;" :: "r"(a),      "f"(ax) : "memory");
            asm volatile("st.shared::cluster.f32 [%0], %1;" :: "r"(a + 4),  "f"(ay) : "memory");
            asm volatile("st.shared::cluster.f32 [%0], %1;" :: "r"(a + 8),  "f"(az) : "memory");
            asm volatile("st.shared::cluster.f32 [%0], %1;" :: "r"(a + 12), "f"(aw) : "memory");
        }

        // cluster rendezvous: release my stores, acquire peer's
        asm volatile("barrier.cluster.arrive.aligned;" ::: "memory");
        asm volatile("barrier.cluster.wait.aligned;"   ::: "memory");

        // --- pointwise LSTM update for my owned (row, column) ---
        if (t < 256) {
            float gi = xg0 + pbuf[par][0][0][pj][pr] + pbuf[par][1][0][pj][pr];
            float gf = xg1 + pbuf[par][0][1][pj][pr] + pbuf[par][1][1][pj][pr];
            float gc = xg2 + pbuf[par][0][2][pj][pr] + pbuf[par][1][2][pj][pr];
            float go = xg3 + pbuf[par][0][3][pj][pr] + pbuf[par][1][3][pj][pr];

            float iv = sigm(gi);
            float fv = sigm(gf);
            float gv = tanhf(gc);
            float ov = sigm(go);

            c = fv * c + iv * gv;
            float h = ov * tanhf(c);

            hbuf[pj][pr] = h;
            g_hs[((size_t)pb * TT + step) * HH + (size_t)(rank * 64 + pj)] = h;
        }
        __syncthreads();   // h visible to all 512 threads before next phase A
    }
}

// ---------------------------------------------------------------------------
// K3: out = hs @ W_out^T.  hs: [BT, 128], W_out: [64, 128].
//   Tile: 32 bt-rows x 64 f per block. smem = 16 KB + 32 KB = 48 KB (static max).
// ---------------------------------------------------------------------------
__global__ __launch_bounds__(256) void k3_proj(
    const float* __restrict__ Wout,
    float* __restrict__ out)
{
    __shared__ __align__(16) float hs_s[32][128];   // 16 KB
    __shared__ __align__(16) float ws[128][64];     // 32 KB, [k][f] transposed

    const int bt0 = blockIdx.x * 32;
    const int t   = threadIdx.x;

    // load hs tile: 4096 floats = 1024 float4
    for (int i = t; i < 1024; i += 256) {
        int row = i >> 5;
        int q   = i & 31;
        ((float4*)hs_s[row])[q] =
            ((const float4*)(g_hs + (size_t)(bt0 + row) * HH))[q];
    }
    // load W_out transposed: 64 f x 128 k = 2048 float4
    for (int i = t; i < 2048; i += 256) {
        int f  = i >> 5;
        int kq = i & 31;
        float4 v = ((const float4*)(Wout + (size_t)f * HH))[kq];
        int k = kq * 4;
        ws[k + 0][f] = v.x;
        ws[k + 1][f] = v.y;
        ws[k + 2][f] = v.z;
        ws[k + 3][f] = v.w;
    }
    __syncthreads();

    const int tf = t & 15;    // f-quad (16 quads = 64 f)
    const int tr = t >> 4;    // 0..15 -> rows tr and tr+16

    float4 acc0 = make_float4(0.f, 0.f, 0.f, 0.f);
    float4 acc1 = make_float4(0.f, 0.f, 0.f, 0.f);

#pragma unroll
    for (int k = 0; k < 128; k++) {
        float4 w4 = *(float4*)&ws[k][tf * 4];
        float h0 = hs_s[tr][k];
        float h1 = hs_s[tr + 16][k];
        acc0.x += h0 * w4.x; acc0.y += h0 * w4.y;
        acc0.z += h0 * w4.z; acc0.w += h0 * w4.w;
        acc1.x += h1 * w4.x; acc1.y += h1 * w4.y;
        acc1.z += h1 * w4.z; acc1.w += h1 * w4.w;
    }

    *(float4*)(out + (size_t)(bt0 + tr) * FF + tf * 4)      = acc0;
    *(float4*)(out + (size_t)(bt0 + tr + 16) * FF + tf * 4) = acc1;
}

// ---------------------------------------------------------------------------
// launch
// ---------------------------------------------------------------------------
extern "C" void kernel_launch(void* const* d_in, const int* in_sizes, int n_in,
                              void* d_out, int out_size)
{
    const float* x    = (const float*)d_in[0];  // [256,1024,64]
    const float* Wih  = (const float*)d_in[1];  // [512,64]
    const float* Whh  = (const float*)d_in[2];  // [512,128]
    const float* bih  = (const float*)d_in[3];  // [512]
    const float* bhh  = (const float*)d_in[4];  // [512]
    const float* Wout = (const float*)d_in[5];  // [64,128]
    float* out = (float*)d_out;                 // [256,1024,64]

    (void)in_sizes; (void)n_in; (void)out_size;

    // K1: xg precompute. Grid: (BT/32) x 4 gate-tiles of 128.
    k1_xgemm<<<dim3((BB * TT) / 32, 4), 256>>>(x, Wih, bih, bhh);

    // K2: persistent recurrence. 64 clusters x 2 CTAs (cluster dims compiled in).
    k2_lstm<<<128, 512>>>(Whh);

    // K3: output projection.
    k3_proj<<<(BB * TT) / 32, 256>>>(Wout, out);
}